// round 5
// baseline (speedup 1.0000x reference)
#include <cuda_runtime.h>

#define NN 50000
#define EE 600000
#define DH 128
#define GG 64
#define LL 3
#define ETOT (EE + NN)

// ---------------- scratch (device globals; referenced by name in device code
// only — kernel_launch makes zero runtime API calls)
__device__ float g_h[NN * DH];       // node features (updated in place per layer)
__device__ float g_hp[NN * DH];      // projected features hp = h @ Wg[i]
__device__ float g_esrc[NN];
__device__ float g_edst[NN];
__device__ int   g_rowptr[NN + 1];
__device__ int   g_cnt[NN];
__device__ int   g_col[ETOT];
__device__ float g_pooled[GG * DH];

// ---------------- init: cnt=1 (self loop), pooled=0 ------------------------
__global__ void k_init() {
    int i = blockIdx.x * blockDim.x + threadIdx.x;
    if (i < NN) g_cnt[i] = 1;
    if (i < GG * DH) g_pooled[i] = 0.f;
}

// ---------------- degree histogram over E real edges -----------------------
// edge_index is INT32 (JAX default x64-disabled downcasts jnp.int64 silently).
__global__ void k_degree(const int* __restrict__ ei) {
    int e = blockIdx.x * blockDim.x + threadIdx.x;
    if (e < EE) {
        int dst = ei[EE + e];
        if ((unsigned)dst < (unsigned)NN)  // defensive: never hard-fault
            atomicAdd(&g_cnt[dst], 1);
    }
}

// ---------------- exclusive scan (single block), resets cnt ----------------
__global__ void k_scan() {
    __shared__ int sh[1024];
    const int t = threadIdx.x;
    const int CH = (NN + 1023) / 1024;  // 49
    int begin = t * CH;
    int end = begin + CH; if (end > NN) end = NN;
    int s = 0;
    for (int i = begin; i < end; i++) s += g_cnt[i];
    sh[t] = s;
    __syncthreads();
    // Hillis-Steele inclusive scan
    for (int off = 1; off < 1024; off <<= 1) {
        int v = (t >= off) ? sh[t - off] : 0;
        __syncthreads();
        sh[t] += v;
        __syncthreads();
    }
    int run = sh[t] - s;  // exclusive prefix for this thread's chunk
    for (int i = begin; i < end; i++) {
        int c = g_cnt[i];
        g_rowptr[i] = run;
        run += c;
        g_cnt[i] = 0;  // reused as fill cursor
    }
    if (t == 1023) g_rowptr[NN] = sh[1023];
}

// ---------------- CSR fill (E real edges + N self loops) -------------------
__global__ void k_fill(const int* __restrict__ ei) {
    int idx = blockIdx.x * blockDim.x + threadIdx.x;
    if (idx >= ETOT) return;
    int src, dst;
    if (idx < EE) {
        src = ei[idx];
        dst = ei[EE + idx];
    } else {
        src = dst = idx - EE;
    }
    if ((unsigned)src >= (unsigned)NN || (unsigned)dst >= (unsigned)NN) return;
    int pos = g_rowptr[dst] + atomicAdd(&g_cnt[dst], 1);
    g_col[pos] = src;
}

// ---------------- GEMM core: O[N,128] = A[N,128] @ W[128,128] --------------
// Block = 256 threads = 8 warps; each warp owns 8 consecutive rows, lanes
// split the 128 output cols into float4 chunks. Optional bias; optional
// fused a_src/a_dst dot products (free warp-reduce in the epilogue).
template <bool DO_BIAS, bool DO_EDOT>
__device__ __forceinline__ void gemm_core(
    const float* __restrict__ A, const float* __restrict__ W,
    const float* __restrict__ bias, float* __restrict__ O,
    const float* __restrict__ asrc, const float* __restrict__ adst)
{
    const int warp = threadIdx.x >> 5;
    const int lane = threadIdx.x & 31;
    const int row0 = blockIdx.x * 64 + warp * 8;

    const float4* W4 = (const float4*)W;
    const float4* Arow[8];
    float4 acc[8];
#pragma unroll
    for (int i = 0; i < 8; i++) {
        int r = row0 + i;
        if (r >= NN) r = 0;  // safe dummy reads; stores predicated below
        Arow[i] = ((const float4*)A) + (size_t)r * 32;
        acc[i] = make_float4(0.f, 0.f, 0.f, 0.f);
    }

#pragma unroll 2
    for (int k4 = 0; k4 < 32; k4++) {
        float4 wv0 = W4[(k4 * 4 + 0) * 32 + lane];
        float4 wv1 = W4[(k4 * 4 + 1) * 32 + lane];
        float4 wv2 = W4[(k4 * 4 + 2) * 32 + lane];
        float4 wv3 = W4[(k4 * 4 + 3) * 32 + lane];
#pragma unroll
        for (int i = 0; i < 8; i++) {
            float4 hv = Arow[i][k4];
            acc[i].x += hv.x * wv0.x; acc[i].y += hv.x * wv0.y;
            acc[i].z += hv.x * wv0.z; acc[i].w += hv.x * wv0.w;
            acc[i].x += hv.y * wv1.x; acc[i].y += hv.y * wv1.y;
            acc[i].z += hv.y * wv1.z; acc[i].w += hv.y * wv1.w;
            acc[i].x += hv.z * wv2.x; acc[i].y += hv.z * wv2.y;
            acc[i].z += hv.z * wv2.z; acc[i].w += hv.z * wv2.w;
            acc[i].x += hv.w * wv3.x; acc[i].y += hv.w * wv3.y;
            acc[i].z += hv.w * wv3.z; acc[i].w += hv.w * wv3.w;
        }
    }

    float4 bias4 = make_float4(0.f, 0.f, 0.f, 0.f);
    if (DO_BIAS) bias4 = ((const float4*)bias)[lane];
    float4 as4 = make_float4(0.f, 0.f, 0.f, 0.f);
    float4 ad4 = make_float4(0.f, 0.f, 0.f, 0.f);
    if (DO_EDOT) {
        as4 = ((const float4*)asrc)[lane];
        ad4 = ((const float4*)adst)[lane];
    }

#pragma unroll
    for (int i = 0; i < 8; i++) {
        int r = row0 + i;
        if (r >= NN) continue;  // uniform across the warp (r independent of lane)
        float4 o = acc[i];
        if (DO_BIAS) { o.x += bias4.x; o.y += bias4.y; o.z += bias4.z; o.w += bias4.w; }
        ((float4*)O)[(size_t)r * 32 + lane] = o;
        if (DO_EDOT) {
            float s = o.x * as4.x + o.y * as4.y + o.z * as4.z + o.w * as4.w;
            float d = o.x * ad4.x + o.y * ad4.y + o.z * ad4.z + o.w * ad4.w;
#pragma unroll
            for (int off = 16; off; off >>= 1) {
                s += __shfl_xor_sync(0xffffffffu, s, off);
                d += __shfl_xor_sync(0xffffffffu, d, off);
            }
            if (lane == 0) { g_esrc[r] = s; g_edst[r] = d; }
        }
    }
}

// mlp1: g_h = x @ W1 + b1   (A is a harness input pointer; O is the global)
__global__ void __launch_bounds__(256) k_gemm_mlp1(
    const float* __restrict__ x, const float* __restrict__ W1,
    const float* __restrict__ b1)
{
    gemm_core<true, false>(x, W1, b1, g_h, nullptr, nullptr);
}

// layer projection: g_hp = g_h @ Wg[i]; fused e_src/e_dst dots
__global__ void __launch_bounds__(256) k_gemm_layer(
    const float* __restrict__ Wgi, const float* __restrict__ asrc,
    const float* __restrict__ adst)
{
    gemm_core<false, true>(g_h, Wgi, nullptr, g_hp, asrc, adst);
}

__device__ __forceinline__ float leaky(float e) {
    return fmaxf(e, 0.2f * e);
}

// ---------------- per-destination-node GAT aggregation ---------------------
// Warp per node: pass1 max, pass2 exp-sum (stash weights in shared),
// pass3 weighted gather-accumulate of g_hp[src] (512B coalesced per edge),
// epilogue: /z + bias, relu, residual, write g_h in place.
__global__ void __launch_bounds__(256) k_agg(const float* __restrict__ bg, int layer) {
    __shared__ float shw[8][128];
    const int warp = threadIdx.x >> 5;
    const int lane = threadIdx.x & 31;
    const int v = blockIdx.x * 8 + warp;
    if (v >= NN) return;

    const int start = g_rowptr[v];
    const int end = g_rowptr[v + 1];
    const float edstv = g_edst[v];

    // pass 1: max
    float m = -1e30f;
    for (int j = start + lane; j < end; j += 32) {
        float e = leaky(g_esrc[g_col[j]] + edstv);
        m = fmaxf(m, e);
    }
#pragma unroll
    for (int off = 16; off; off >>= 1)
        m = fmaxf(m, __shfl_xor_sync(0xffffffffu, m, off));

    // pass 2: exp and sum
    float z = 0.f;
    {
        int idx = lane;
        for (int j = start + lane; j < end; j += 32, idx += 32) {
            float e = leaky(g_esrc[g_col[j]] + edstv);
            float wj = __expf(e - m);
            z += wj;
            if (idx < 128) shw[warp][idx] = wj;
        }
    }
#pragma unroll
    for (int off = 16; off; off >>= 1)
        z += __shfl_xor_sync(0xffffffffu, z, off);
    __syncwarp();

    // pass 3: weighted accumulation, lanes split the 128 features (float4 each)
    float4 acc = make_float4(0.f, 0.f, 0.f, 0.f);
    const int deg = end - start;
    const float4* HP4 = (const float4*)g_hp;
    for (int j = 0; j < deg; j++) {
        int src = g_col[start + j];     // uniform (broadcast) load
        float wj;
        if (j < 128) {
            wj = shw[warp][j];
        } else {  // deg>128 is astronomically rare (mean deg ~13); recompute
            float e = leaky(g_esrc[src] + edstv);
            wj = __expf(e - m);
        }
        float4 hv = HP4[(size_t)src * 32 + lane];
        acc.x += wj * hv.x; acc.y += wj * hv.y;
        acc.z += wj * hv.z; acc.w += wj * hv.w;
    }

    const float inv = 1.0f / z;
    float4 b4 = ((const float4*)(bg + layer * DH))[lane];
    float4 h4 = ((const float4*)g_h)[(size_t)v * 32 + lane];
    float4 o;
    o.x = fmaxf(acc.x * inv + b4.x, 0.f) + h4.x;
    o.y = fmaxf(acc.y * inv + b4.y, 0.f) + h4.y;
    o.z = fmaxf(acc.z * inv + b4.z, 0.f) + h4.z;
    o.w = fmaxf(acc.w * inv + b4.w, 0.f) + h4.w;
    ((float4*)g_h)[(size_t)v * 32 + lane] = o;
}

// ---------------- global add pool (batch is sorted, INT32) -----------------
__global__ void k_pool(const int* __restrict__ batch) {
    const int f = threadIdx.x;  // 128 threads, one per feature
    const int v0 = blockIdx.x * 256;
    int v1 = v0 + 256; if (v1 > NN) v1 = NN;
    int curg = batch[v0];
    float local = 0.f;
    for (int v = v0; v < v1; v++) {
        int g = batch[v];  // broadcast across threads
        if (g != curg) {
            if ((unsigned)curg < (unsigned)GG)
                atomicAdd(&g_pooled[curg * DH + f], local);
            local = 0.f;
            curg = g;
        }
        local += g_h[(size_t)v * DH + f];
    }
    if ((unsigned)curg < (unsigned)GG)
        atomicAdd(&g_pooled[curg * DH + f], local);
}

// ---------------- out = pooled @ W2 + b2 -----------------------------------
__global__ void k_final(const float* __restrict__ W2, const float* __restrict__ b2,
                        float* __restrict__ out) {
    const int g = blockIdx.x;   // 64
    const int o = threadIdx.x;  // 64
    float s = b2[o];
#pragma unroll 4
    for (int k = 0; k < DH; k++)
        s += g_pooled[g * DH + k] * W2[k * 64 + o];
    out[g * 64 + o] = s;
}

// ---------------- launch: kernel launches ONLY (graph-capturable) ----------
extern "C" void kernel_launch(void* const* d_in, const int* in_sizes, int n_in,
                              void* d_out, int out_size) {
    const float* x  = (const float*)d_in[0];
    const int*   ei = (const int*)d_in[1];       // int32 (JAX default)
    const int*   batch = (const int*)d_in[2];    // int32 (JAX default)
    const float* W1 = (const float*)d_in[3];
    const float* b1 = (const float*)d_in[4];
    const float* Wg = (const float*)d_in[5];
    const float* asrc = (const float*)d_in[6];
    const float* adst = (const float*)d_in[7];
    const float* bg = (const float*)d_in[8];
    const float* W2 = (const float*)d_in[9];
    const float* b2 = (const float*)d_in[10];
    float* out = (float*)d_out;

    // CSR build (depends only on edge_index; rebuilt each call)
    k_init<<<(NN + 255) / 256, 256>>>();
    k_degree<<<(EE + 255) / 256, 256>>>(ei);
    k_scan<<<1, 1024>>>();
    k_fill<<<(ETOT + 255) / 256, 256>>>(ei);

    const int GEMM_GRID = (NN + 63) / 64;

    // mlp1: g_h = x @ W1 + b1
    k_gemm_mlp1<<<GEMM_GRID, 256>>>(x, W1, b1);

    // 3 GAT layers
    for (int i = 0; i < LL; i++) {
        k_gemm_layer<<<GEMM_GRID, 256>>>(Wg + (size_t)i * DH * DH,
                                         asrc + (size_t)i * DH,
                                         adst + (size_t)i * DH);
        k_agg<<<(NN + 7) / 8, 256>>>(bg, i);
    }

    // pooling + output head
    k_pool<<<(NN + 255) / 256, 128>>>(batch);
    k_final<<<GG, 64>>>(W2, b2, out);
}

// round 6
// speedup vs baseline: 1.3320x; 1.3320x over previous
#include <cuda_runtime.h>
#include <cstdint>

#define NN 50000
#define EE 600000
#define DH 128
#define GG 64
#define LL 3
#define ETOT (EE + NN)

// ---------------- scratch (device globals; referenced by name only) --------
__device__ float g_h[NN * DH];        // node features (updated per layer)
__device__ float g_hp[NN * DH];       // projected features hp = h @ Wg[i]
__device__ float g_esrc[NN];
__device__ float g_edst[NN];
__device__ int   g_rowptr[NN + 1];
__device__ int   g_cnt[NN];
__device__ int   g_col[ETOT];
__device__ float g_pooled[GG * DH];
// W fragments for mma.m16n8k8 tf32, B-operand layout:
// [mat(4)][ntile(16)][kstep(16)][lane(32)] -> uint2{b0,b1}
__device__ uint2 g_wfrag[4 * 16 * 16 * 32];

// ---------------- helpers --------------------------------------------------
__device__ __forceinline__ uint32_t f2tf32(float f) {
    uint32_t r;
    asm("cvt.rna.tf32.f32 %0, %1;" : "=r"(r) : "f"(f));
    return r;
}

__device__ __forceinline__ void mma_tf32(
    float& c0, float& c1, float& c2, float& c3,
    uint32_t a0, uint32_t a1, uint32_t a2, uint32_t a3,
    uint32_t b0, uint32_t b1)
{
    asm volatile(
        "mma.sync.aligned.m16n8k8.row.col.f32.tf32.tf32.f32 "
        "{%0,%1,%2,%3}, {%4,%5,%6,%7}, {%8,%9}, {%0,%1,%2,%3};\n"
        : "+f"(c0), "+f"(c1), "+f"(c2), "+f"(c3)
        : "r"(a0), "r"(a1), "r"(a2), "r"(a3), "r"(b0), "r"(b1));
}

__device__ __forceinline__ float leaky(float e) {
    return fmaxf(e, 0.2f * e);
}

// ---------------- init: cnt=1 (self loop), pooled=0 ------------------------
__global__ void k_init() {
    int i = blockIdx.x * blockDim.x + threadIdx.x;
    if (i < NN) g_cnt[i] = 1;
    if (i < GG * DH) g_pooled[i] = 0.f;
}

// ---------------- degree histogram (edge_index is int32) -------------------
__global__ void k_degree(const int* __restrict__ ei) {
    int e = blockIdx.x * blockDim.x + threadIdx.x;
    if (e < EE) {
        int dst = ei[EE + e];
        if ((unsigned)dst < (unsigned)NN)
            atomicAdd(&g_cnt[dst], 1);
    }
}

// ---------------- exclusive scan (single block), resets cnt ----------------
__global__ void k_scan() {
    __shared__ int sh[1024];
    const int t = threadIdx.x;
    const int CH = (NN + 1023) / 1024;
    int begin = t * CH;
    int end = begin + CH; if (end > NN) end = NN;
    int s = 0;
    for (int i = begin; i < end; i++) s += g_cnt[i];
    sh[t] = s;
    __syncthreads();
    for (int off = 1; off < 1024; off <<= 1) {
        int v = (t >= off) ? sh[t - off] : 0;
        __syncthreads();
        sh[t] += v;
        __syncthreads();
    }
    int run = sh[t] - s;
    for (int i = begin; i < end; i++) {
        int c = g_cnt[i];
        g_rowptr[i] = run;
        run += c;
        g_cnt[i] = 0;
    }
    if (t == 1023) g_rowptr[NN] = sh[1023];
}

// ---------------- CSR fill (E real edges + N self loops) -------------------
__global__ void k_fill(const int* __restrict__ ei) {
    int idx = blockIdx.x * blockDim.x + threadIdx.x;
    if (idx >= ETOT) return;
    int src, dst;
    if (idx < EE) {
        src = ei[idx];
        dst = ei[EE + idx];
    } else {
        src = dst = idx - EE;
    }
    if ((unsigned)src >= (unsigned)NN || (unsigned)dst >= (unsigned)NN) return;
    int pos = g_rowptr[dst] + atomicAdd(&g_cnt[dst], 1);
    g_col[pos] = src;
}

// ---------------- W -> mma B-fragment layout (tf32-rounded) ----------------
// b0 = W[ks*8 + t4][nt*8 + g], b1 = W[ks*8 + t4 + 4][nt*8 + g]
__global__ void k_wprep(const float* __restrict__ W1, const float* __restrict__ Wg) {
    int idx = blockIdx.x * blockDim.x + threadIdx.x;  // 4 * 16*16*32
    if (idx >= 4 * 8192) return;
    int mat = idx >> 13;
    int rem = idx & 8191;
    int nt = rem >> 9;
    int ks = (rem >> 5) & 15;
    int lane = rem & 31;
    int g = lane >> 2, t4 = lane & 3;
    const float* W = (mat == 0) ? W1 : (Wg + (size_t)(mat - 1) * DH * DH);
    int col = nt * 8 + g;
    float w0 = W[(ks * 8 + t4) * DH + col];
    float w1 = W[(ks * 8 + t4 + 4) * DH + col];
    uint2 b;
    b.x = f2tf32(w0);
    b.y = f2tf32(w1);
    g_wfrag[idx] = b;
}

// ---------------- tensor-core GEMM: O[N,128] = A[N,128] @ W ---------------
// 256 threads = 8 warps. Block tile 128x128. Warp tile 32x64:
// warp w -> mrow0 = (w&3)*32, ncol0 = (w>>2)*64. mma m16n8k8 tf32.
__global__ void __launch_bounds__(256) k_gemm_tc(
    const float* __restrict__ A_ext,   // x for mlp1, else nullptr (use g_h)
    const float* __restrict__ bias,    // b1 for mlp1, else nullptr
    int fragBase,                      // 0 = W1, 1+i = Wg[i]
    int toH)                           // 1: write g_h, 0: write g_hp
{
    const int warp = threadIdx.x >> 5;
    const int lane = threadIdx.x & 31;
    const int g = lane >> 2, t4 = lane & 3;
    const int mrow0 = blockIdx.x * 128 + (warp & 3) * 32;
    const int ncol0 = (warp >> 2) * 64;   // 0 or 64
    const int ntbase = fragBase * 16 + (ncol0 >> 3);

    const float* __restrict__ A = A_ext ? A_ext : g_h;
    float* __restrict__ O = toH ? g_h : g_hp;

    float c[2][8][4];
#pragma unroll
    for (int mt = 0; mt < 2; mt++)
#pragma unroll
        for (int nt = 0; nt < 8; nt++)
#pragma unroll
            for (int q = 0; q < 4; q++) c[mt][nt][q] = 0.f;

    // A row indices (clamped for the ragged last block; stores predicated)
    int ra[2][2];
#pragma unroll
    for (int mt = 0; mt < 2; mt++) {
        int r0 = mrow0 + mt * 16 + g;
        int r1 = r0 + 8;
        ra[mt][0] = (r0 < NN) ? r0 : 0;
        ra[mt][1] = (r1 < NN) ? r1 : 0;
    }

#pragma unroll 4
    for (int ks = 0; ks < 16; ks++) {
        const int k0 = ks * 8;
        uint32_t a[2][4];
#pragma unroll
        for (int mt = 0; mt < 2; mt++) {
            a[mt][0] = f2tf32(__ldg(A + (size_t)ra[mt][0] * DH + k0 + t4));
            a[mt][1] = f2tf32(__ldg(A + (size_t)ra[mt][1] * DH + k0 + t4));
            a[mt][2] = f2tf32(__ldg(A + (size_t)ra[mt][0] * DH + k0 + t4 + 4));
            a[mt][3] = f2tf32(__ldg(A + (size_t)ra[mt][1] * DH + k0 + t4 + 4));
        }
#pragma unroll
        for (int nt = 0; nt < 8; nt++) {
            uint2 b = __ldg(&g_wfrag[((size_t)(ntbase + nt) * 16 + ks) * 32 + lane]);
            mma_tf32(c[0][nt][0], c[0][nt][1], c[0][nt][2], c[0][nt][3],
                     a[0][0], a[0][1], a[0][2], a[0][3], b.x, b.y);
            mma_tf32(c[1][nt][0], c[1][nt][1], c[1][nt][2], c[1][nt][3],
                     a[1][0], a[1][1], a[1][2], a[1][3], b.x, b.y);
        }
    }

    // epilogue: c0,c1 -> (row g, cols 2t4,2t4+1); c2,c3 -> row g+8
#pragma unroll
    for (int mt = 0; mt < 2; mt++) {
#pragma unroll
        for (int nt = 0; nt < 8; nt++) {
            int col = ncol0 + nt * 8 + 2 * t4;
            float bx = 0.f, by = 0.f;
            if (bias) { bx = __ldg(bias + col); by = __ldg(bias + col + 1); }
            int r0 = mrow0 + mt * 16 + g;
            int r1 = r0 + 8;
            if (r0 < NN) {
                float2 v = make_float2(c[mt][nt][0] + bx, c[mt][nt][1] + by);
                *(float2*)(O + (size_t)r0 * DH + col) = v;
            }
            if (r1 < NN) {
                float2 v = make_float2(c[mt][nt][2] + bx, c[mt][nt][3] + by);
                *(float2*)(O + (size_t)r1 * DH + col) = v;
            }
        }
    }
}

// ---------------- e_src/e_dst dots over g_hp -------------------------------
__global__ void __launch_bounds__(256) k_edot(
    const float* __restrict__ asrc, const float* __restrict__ adst)
{
    const int warp = threadIdx.x >> 5;
    const int lane = threadIdx.x & 31;
    const int r0 = blockIdx.x * 64 + warp * 8;
    float4 as4 = ((const float4*)asrc)[lane];
    float4 ad4 = ((const float4*)adst)[lane];
    const float4* HP4 = (const float4*)g_hp;
#pragma unroll
    for (int i = 0; i < 8; i++) {
        int r = r0 + i;
        if (r >= NN) break;
        float4 h = HP4[(size_t)r * 32 + lane];
        float s = h.x * as4.x + h.y * as4.y + h.z * as4.z + h.w * as4.w;
        float d = h.x * ad4.x + h.y * ad4.y + h.z * ad4.z + h.w * ad4.w;
#pragma unroll
        for (int off = 16; off; off >>= 1) {
            s += __shfl_xor_sync(0xffffffffu, s, off);
            d += __shfl_xor_sync(0xffffffffu, d, off);
        }
        if (lane == 0) { g_esrc[r] = s; g_edst[r] = d; }
    }
}

// ---------------- fused single-pass GAT aggregation ------------------------
// Softmax without max-shift (e is O(10); exp safe in fp32; alpha identical).
// Every lane computes the same w_j, so z is lane-uniform: no reductions.
__global__ void __launch_bounds__(256) k_agg(const float* __restrict__ bg, int layer) {
    const int warp = threadIdx.x >> 5;
    const int lane = threadIdx.x & 31;
    const int v = blockIdx.x * 8 + warp;
    if (v >= NN) return;

    const int start = g_rowptr[v];
    const int end = g_rowptr[v + 1];
    const float edstv = g_edst[v];

    float4 acc = make_float4(0.f, 0.f, 0.f, 0.f);
    float z = 0.f;
    const float4* HP4 = (const float4*)g_hp;
    for (int j = start; j < end; j++) {
        int src = g_col[j];                        // uniform broadcast load
        float wj = __expf(leaky(g_esrc[src] + edstv));
        z += wj;
        float4 hv = HP4[(size_t)src * 32 + lane];  // 512B coalesced per edge
        acc.x += wj * hv.x; acc.y += wj * hv.y;
        acc.z += wj * hv.z; acc.w += wj * hv.w;
    }

    const float inv = 1.0f / z;
    float4 b4 = ((const float4*)(bg + layer * DH))[lane];
    float4 h4 = ((const float4*)g_h)[(size_t)v * 32 + lane];
    float4 o;
    o.x = fmaxf(acc.x * inv + b4.x, 0.f) + h4.x;
    o.y = fmaxf(acc.y * inv + b4.y, 0.f) + h4.y;
    o.z = fmaxf(acc.z * inv + b4.z, 0.f) + h4.z;
    o.w = fmaxf(acc.w * inv + b4.w, 0.f) + h4.w;
    ((float4*)g_h)[(size_t)v * 32 + lane] = o;
}

// ---------------- global add pool (batch is sorted, int32) -----------------
__global__ void k_pool(const int* __restrict__ batch) {
    const int f = threadIdx.x;  // 128 threads, one per feature
    const int v0 = blockIdx.x * 256;
    int v1 = v0 + 256; if (v1 > NN) v1 = NN;
    int curg = batch[v0];
    float local = 0.f;
    for (int v = v0; v < v1; v++) {
        int g = batch[v];
        if (g != curg) {
            if ((unsigned)curg < (unsigned)GG)
                atomicAdd(&g_pooled[curg * DH + f], local);
            local = 0.f;
            curg = g;
        }
        local += g_h[(size_t)v * DH + f];
    }
    if ((unsigned)curg < (unsigned)GG)
        atomicAdd(&g_pooled[curg * DH + f], local);
}

// ---------------- out = pooled @ W2 + b2 -----------------------------------
__global__ void k_final(const float* __restrict__ W2, const float* __restrict__ b2,
                        float* __restrict__ out) {
    const int g = blockIdx.x;   // 64
    const int o = threadIdx.x;  // 64
    float s = b2[o];
#pragma unroll 4
    for (int k = 0; k < DH; k++)
        s += g_pooled[g * DH + k] * W2[k * 64 + o];
    out[g * 64 + o] = s;
}

// ---------------- launch: kernel launches ONLY (graph-capturable) ----------
extern "C" void kernel_launch(void* const* d_in, const int* in_sizes, int n_in,
                              void* d_out, int out_size) {
    const float* x  = (const float*)d_in[0];
    const int*   ei = (const int*)d_in[1];       // int32 (JAX default)
    const int*   batch = (const int*)d_in[2];    // int32 (JAX default)
    const float* W1 = (const float*)d_in[3];
    const float* b1 = (const float*)d_in[4];
    const float* Wg = (const float*)d_in[5];
    const float* asrc = (const float*)d_in[6];
    const float* adst = (const float*)d_in[7];
    const float* bg = (const float*)d_in[8];
    const float* W2 = (const float*)d_in[9];
    const float* b2 = (const float*)d_in[10];
    float* out = (float*)d_out;

    // CSR build
    k_init<<<(NN + 255) / 256, 256>>>();
    k_degree<<<(EE + 255) / 256, 256>>>(ei);
    k_scan<<<1, 1024>>>();
    k_fill<<<(ETOT + 255) / 256, 256>>>(ei);

    // W fragment prep (all 4 matrices)
    k_wprep<<<(4 * 8192 + 255) / 256, 256>>>(W1, Wg);

    const int TC_GRID = (NN + 127) / 128;  // 391

    // mlp1: g_h = x @ W1 + b1
    k_gemm_tc<<<TC_GRID, 256>>>(x, b1, 0, 1);

    // 3 GAT layers
    for (int i = 0; i < LL; i++) {
        k_gemm_tc<<<TC_GRID, 256>>>(nullptr, nullptr, 1 + i, 0);
        k_edot<<<(NN + 63) / 64, 256>>>(asrc + (size_t)i * DH,
                                        adst + (size_t)i * DH);
        k_agg<<<(NN + 7) / 8, 256>>>(bg, i);
    }

    // pooling + output head
    k_pool<<<(NN + 255) / 256, 128>>>(batch);
    k_final<<<GG, 64>>>(W2, b2, out);
}

// round 7
// speedup vs baseline: 1.4405x; 1.0815x over previous
#include <cuda_runtime.h>
#include <cstdint>

#define NN 50000
#define EE 600000
#define DH 128
#define GG 64
#define LL 3
#define ETOT (EE + NN)

// ---------------- scratch (device globals; referenced by name only) --------
__device__ float g_h[NN * DH];        // node features (updated per layer)
__device__ float g_hp[NN * DH];       // projected features hp = h @ Wg[i]
__device__ float g_esrc[NN];
__device__ float g_edst[NN];
__device__ int   g_rowptr[NN + 1];
__device__ int   g_cnt[NN];
__device__ int   g_col[ETOT];
__device__ float g_pooled[GG * DH];
// W fragments for mma.m16n8k8 tf32, B-operand layout:
// [mat(4)][ntile(16)][kstep(16)][lane(32)] -> uint2{b0,b1}
__device__ uint2 g_wfrag[4 * 16 * 16 * 32];

// ---------------- helpers --------------------------------------------------
__device__ __forceinline__ uint32_t f2tf32(float f) {
    uint32_t r;
    asm("cvt.rna.tf32.f32 %0, %1;" : "=r"(r) : "f"(f));
    return r;
}

__device__ __forceinline__ void mma_tf32(
    float& c0, float& c1, float& c2, float& c3,
    uint32_t a0, uint32_t a1, uint32_t a2, uint32_t a3,
    uint32_t b0, uint32_t b1)
{
    asm volatile(
        "mma.sync.aligned.m16n8k8.row.col.f32.tf32.tf32.f32 "
        "{%0,%1,%2,%3}, {%4,%5,%6,%7}, {%8,%9}, {%0,%1,%2,%3};\n"
        : "+f"(c0), "+f"(c1), "+f"(c2), "+f"(c3)
        : "r"(a0), "r"(a1), "r"(a2), "r"(a3), "r"(b0), "r"(b1));
}

__device__ __forceinline__ float leaky(float e) {
    return fmaxf(e, 0.2f * e);
}

// ---------------- init: cnt=1 (self loop), pooled=0 ------------------------
__global__ void k_init() {
    int i = blockIdx.x * blockDim.x + threadIdx.x;
    if (i < NN) g_cnt[i] = 1;
    if (i < GG * DH) g_pooled[i] = 0.f;
}

// ---------------- degree histogram (edge_index is int32) -------------------
__global__ void k_degree(const int* __restrict__ ei) {
    int e = blockIdx.x * blockDim.x + threadIdx.x;
    if (e < EE) {
        int dst = ei[EE + e];
        if ((unsigned)dst < (unsigned)NN)
            atomicAdd(&g_cnt[dst], 1);
    }
}

// ---------------- exclusive scan (single block), resets cnt ----------------
__global__ void k_scan() {
    __shared__ int sh[1024];
    const int t = threadIdx.x;
    const int CH = (NN + 1023) / 1024;
    int begin = t * CH;
    int end = begin + CH; if (end > NN) end = NN;
    int s = 0;
    for (int i = begin; i < end; i++) s += g_cnt[i];
    sh[t] = s;
    __syncthreads();
    for (int off = 1; off < 1024; off <<= 1) {
        int v = (t >= off) ? sh[t - off] : 0;
        __syncthreads();
        sh[t] += v;
        __syncthreads();
    }
    int run = sh[t] - s;
    for (int i = begin; i < end; i++) {
        int c = g_cnt[i];
        g_rowptr[i] = run;
        run += c;
        g_cnt[i] = 0;
    }
    if (t == 1023) g_rowptr[NN] = sh[1023];
}

// ---------------- CSR fill (E real edges + N self loops) -------------------
__global__ void k_fill(const int* __restrict__ ei) {
    int idx = blockIdx.x * blockDim.x + threadIdx.x;
    if (idx >= ETOT) return;
    int src, dst;
    if (idx < EE) {
        src = ei[idx];
        dst = ei[EE + idx];
    } else {
        src = dst = idx - EE;
    }
    if ((unsigned)src >= (unsigned)NN || (unsigned)dst >= (unsigned)NN) return;
    int pos = g_rowptr[dst] + atomicAdd(&g_cnt[dst], 1);
    g_col[pos] = src;
}

// ---------------- W -> mma B-fragment layout (tf32-rounded) ----------------
// b0 = W[ks*8 + t4][nt*8 + g], b1 = W[ks*8 + t4 + 4][nt*8 + g]
__global__ void k_wprep(const float* __restrict__ W1, const float* __restrict__ Wg) {
    int idx = blockIdx.x * blockDim.x + threadIdx.x;  // 4 * 16*16*32
    if (idx >= 4 * 8192) return;
    int mat = idx >> 13;
    int rem = idx & 8191;
    int nt = rem >> 9;
    int ks = (rem >> 5) & 15;
    int lane = rem & 31;
    int g = lane >> 2, t4 = lane & 3;
    const float* W = (mat == 0) ? W1 : (Wg + (size_t)(mat - 1) * DH * DH);
    int col = nt * 8 + g;
    float w0 = W[(ks * 8 + t4) * DH + col];
    float w1 = W[(ks * 8 + t4 + 4) * DH + col];
    uint2 b;
    b.x = f2tf32(w0);
    b.y = f2tf32(w1);
    g_wfrag[idx] = b;
}

// ---------------- tensor-core GEMM: O[N,128] = A[N,128] @ W ----------------
// 128 threads = 4 warps. Block tile 128 rows; warp tile 32 rows x FULL 128
// cols -> each warp owns complete output rows, so the attention dot products
// (e_src = hp.a_src, e_dst = hp.a_dst) reduce with two quad-shuffles in the
// epilogue: no extra kernel, no atomics, no re-read of hp.
template <bool DO_BIAS, bool DO_EDOT>
__device__ __forceinline__ void gemm_core(
    const float* __restrict__ A, const float* __restrict__ bias,
    const float* __restrict__ asrc, const float* __restrict__ adst,
    int fragBase, float* __restrict__ O)
{
    const int warp = threadIdx.x >> 5;
    const int lane = threadIdx.x & 31;
    const int g = lane >> 2, t4 = lane & 3;
    const int mrow0 = blockIdx.x * 128 + warp * 32;
    const int ntbase = fragBase * 16;

    float c[2][16][4];
#pragma unroll
    for (int mt = 0; mt < 2; mt++)
#pragma unroll
        for (int nt = 0; nt < 16; nt++)
#pragma unroll
            for (int q = 0; q < 4; q++) c[mt][nt][q] = 0.f;

    // A row indices (clamped for the ragged last block; stores predicated)
    int ra[2][2];
#pragma unroll
    for (int mt = 0; mt < 2; mt++) {
        int r0 = mrow0 + mt * 16 + g;
        int r1 = r0 + 8;
        ra[mt][0] = (r0 < NN) ? r0 : 0;
        ra[mt][1] = (r1 < NN) ? r1 : 0;
    }

#pragma unroll 2
    for (int ks = 0; ks < 16; ks++) {
        const int k0 = ks * 8;
        uint32_t a[2][4];
#pragma unroll
        for (int mt = 0; mt < 2; mt++) {
            a[mt][0] = f2tf32(__ldg(A + (size_t)ra[mt][0] * DH + k0 + t4));
            a[mt][1] = f2tf32(__ldg(A + (size_t)ra[mt][1] * DH + k0 + t4));
            a[mt][2] = f2tf32(__ldg(A + (size_t)ra[mt][0] * DH + k0 + t4 + 4));
            a[mt][3] = f2tf32(__ldg(A + (size_t)ra[mt][1] * DH + k0 + t4 + 4));
        }
#pragma unroll
        for (int nt = 0; nt < 16; nt++) {
            uint2 b = __ldg(&g_wfrag[((size_t)(ntbase + nt) * 16 + ks) * 32 + lane]);
            mma_tf32(c[0][nt][0], c[0][nt][1], c[0][nt][2], c[0][nt][3],
                     a[0][0], a[0][1], a[0][2], a[0][3], b.x, b.y);
            mma_tf32(c[1][nt][0], c[1][nt][1], c[1][nt][2], c[1][nt][3],
                     a[1][0], a[1][1], a[1][2], a[1][3], b.x, b.y);
        }
    }

    // epilogue: c0,c1 -> (row g, cols 2t4,2t4+1); c2,c3 -> row g+8
#pragma unroll
    for (int mt = 0; mt < 2; mt++) {
        const int r0 = mrow0 + mt * 16 + g;
        const int r1 = r0 + 8;
        float s0 = 0.f, d0 = 0.f, s1 = 0.f, d1 = 0.f;
#pragma unroll
        for (int nt = 0; nt < 16; nt++) {
            const int col = nt * 8 + 2 * t4;
            float bx = 0.f, by = 0.f;
            if (DO_BIAS) { bx = __ldg(bias + col); by = __ldg(bias + col + 1); }
            if (r0 < NN) {
                float2 v = make_float2(c[mt][nt][0] + bx, c[mt][nt][1] + by);
                *(float2*)(O + (size_t)r0 * DH + col) = v;
            }
            if (r1 < NN) {
                float2 v = make_float2(c[mt][nt][2] + bx, c[mt][nt][3] + by);
                *(float2*)(O + (size_t)r1 * DH + col) = v;
            }
            if (DO_EDOT) {
                float2 as = *(const float2*)(asrc + col);
                float2 ad = *(const float2*)(adst + col);
                s0 += c[mt][nt][0] * as.x + c[mt][nt][1] * as.y;
                d0 += c[mt][nt][0] * ad.x + c[mt][nt][1] * ad.y;
                s1 += c[mt][nt][2] * as.x + c[mt][nt][3] * as.y;
                d1 += c[mt][nt][2] * ad.x + c[mt][nt][3] * ad.y;
            }
        }
        if (DO_EDOT) {
            // reduce across the 4 t4 lanes of the quad (lanes g*4 .. g*4+3)
#pragma unroll
            for (int off = 1; off <= 2; off <<= 1) {
                s0 += __shfl_xor_sync(0xffffffffu, s0, off);
                d0 += __shfl_xor_sync(0xffffffffu, d0, off);
                s1 += __shfl_xor_sync(0xffffffffu, s1, off);
                d1 += __shfl_xor_sync(0xffffffffu, d1, off);
            }
            if (t4 == 0) {
                if (r0 < NN) { g_esrc[r0] = s0; g_edst[r0] = d0; }
                if (r1 < NN) { g_esrc[r1] = s1; g_edst[r1] = d1; }
            }
        }
    }
}

// mlp1: g_h = x @ W1 + b1
__global__ void __launch_bounds__(128) k_gemm_mlp1(
    const float* __restrict__ x, const float* __restrict__ b1)
{
    gemm_core<true, false>(x, b1, nullptr, nullptr, 0, g_h);
}

// layer projection: g_hp = g_h @ Wg[i], fused e_src/e_dst dots
__global__ void __launch_bounds__(128) k_gemm_layer(
    const float* __restrict__ asrc, const float* __restrict__ adst, int fragBase)
{
    gemm_core<false, true>(g_h, nullptr, asrc, adst, fragBase, g_hp);
}

// ---------------- fused single-pass GAT aggregation ------------------------
// Softmax without max-shift (e is O(10); exp safe in fp32; alpha identical).
// Every lane computes the same w_j, so z is lane-uniform: no reductions.
// 4x unrolled: 4 independent gather chains in flight (MLP ~4 instead of ~1).
__global__ void __launch_bounds__(256) k_agg(const float* __restrict__ bg, int layer) {
    const int warp = threadIdx.x >> 5;
    const int lane = threadIdx.x & 31;
    const int v = blockIdx.x * 8 + warp;
    if (v >= NN) return;

    const int start = g_rowptr[v];
    const int end = g_rowptr[v + 1];
    const float edstv = g_edst[v];

    float4 acc = make_float4(0.f, 0.f, 0.f, 0.f);
    float z = 0.f;
    const float4* __restrict__ HP4 = (const float4*)g_hp;
    const int* __restrict__ col = g_col;

    int j = start;
    for (; j + 4 <= end; j += 4) {
        int s0 = col[j], s1 = col[j + 1], s2 = col[j + 2], s3 = col[j + 3];
        float w0 = __expf(leaky(g_esrc[s0] + edstv));
        float w1 = __expf(leaky(g_esrc[s1] + edstv));
        float w2 = __expf(leaky(g_esrc[s2] + edstv));
        float w3 = __expf(leaky(g_esrc[s3] + edstv));
        float4 h0 = HP4[(size_t)s0 * 32 + lane];
        float4 h1 = HP4[(size_t)s1 * 32 + lane];
        float4 h2 = HP4[(size_t)s2 * 32 + lane];
        float4 h3 = HP4[(size_t)s3 * 32 + lane];
        z += (w0 + w1) + (w2 + w3);
        acc.x += w0 * h0.x + w1 * h1.x + w2 * h2.x + w3 * h3.x;
        acc.y += w0 * h0.y + w1 * h1.y + w2 * h2.y + w3 * h3.y;
        acc.z += w0 * h0.z + w1 * h1.z + w2 * h2.z + w3 * h3.z;
        acc.w += w0 * h0.w + w1 * h1.w + w2 * h2.w + w3 * h3.w;
    }
    for (; j < end; j++) {
        int src = col[j];
        float wj = __expf(leaky(g_esrc[src] + edstv));
        z += wj;
        float4 hv = HP4[(size_t)src * 32 + lane];
        acc.x += wj * hv.x; acc.y += wj * hv.y;
        acc.z += wj * hv.z; acc.w += wj * hv.w;
    }

    const float inv = 1.0f / z;
    float4 b4 = ((const float4*)(bg + layer * DH))[lane];
    float4 h4 = ((const float4*)g_h)[(size_t)v * 32 + lane];
    float4 o;
    o.x = fmaxf(acc.x * inv + b4.x, 0.f) + h4.x;
    o.y = fmaxf(acc.y * inv + b4.y, 0.f) + h4.y;
    o.z = fmaxf(acc.z * inv + b4.z, 0.f) + h4.z;
    o.w = fmaxf(acc.w * inv + b4.w, 0.f) + h4.w;
    ((float4*)g_h)[(size_t)v * 32 + lane] = o;
}

// ---------------- global add pool (batch is sorted, int32) -----------------
__global__ void k_pool(const int* __restrict__ batch) {
    const int f = threadIdx.x;  // 128 threads, one per feature
    const int v0 = blockIdx.x * 256;
    int v1 = v0 + 256; if (v1 > NN) v1 = NN;
    int curg = batch[v0];
    float local = 0.f;
    for (int v = v0; v < v1; v++) {
        int g = batch[v];
        if (g != curg) {
            if ((unsigned)curg < (unsigned)GG)
                atomicAdd(&g_pooled[curg * DH + f], local);
            local = 0.f;
            curg = g;
        }
        local += g_h[(size_t)v * DH + f];
    }
    if ((unsigned)curg < (unsigned)GG)
        atomicAdd(&g_pooled[curg * DH + f], local);
}

// ---------------- out = pooled @ W2 + b2 -----------------------------------
__global__ void k_final(const float* __restrict__ W2, const float* __restrict__ b2,
                        float* __restrict__ out) {
    const int g = blockIdx.x;   // 64
    const int o = threadIdx.x;  // 64
    float s = b2[o];
#pragma unroll 4
    for (int k = 0; k < DH; k++)
        s += g_pooled[g * DH + k] * W2[k * 64 + o];
    out[g * 64 + o] = s;
}

// ---------------- launch: kernel launches ONLY (graph-capturable) ----------
extern "C" void kernel_launch(void* const* d_in, const int* in_sizes, int n_in,
                              void* d_out, int out_size) {
    const float* x  = (const float*)d_in[0];
    const int*   ei = (const int*)d_in[1];       // int32 (JAX default)
    const int*   batch = (const int*)d_in[2];    // int32 (JAX default)
    const float* W1 = (const float*)d_in[3];
    const float* b1 = (const float*)d_in[4];
    const float* Wg = (const float*)d_in[5];
    const float* asrc = (const float*)d_in[6];
    const float* adst = (const float*)d_in[7];
    const float* bg = (const float*)d_in[8];
    const float* W2 = (const float*)d_in[9];
    const float* b2 = (const float*)d_in[10];
    float* out = (float*)d_out;

    // CSR build
    k_init<<<(NN + 255) / 256, 256>>>();
    k_degree<<<(EE + 255) / 256, 256>>>(ei);
    k_scan<<<1, 1024>>>();
    k_fill<<<(ETOT + 255) / 256, 256>>>(ei);

    // W fragment prep (all 4 matrices)
    k_wprep<<<(4 * 8192 + 255) / 256, 256>>>(W1, Wg);

    const int TC_GRID = (NN + 127) / 128;  // 391

    // mlp1: g_h = x @ W1 + b1
    k_gemm_mlp1<<<TC_GRID, 128>>>(x, b1);

    // 3 GAT layers
    for (int i = 0; i < LL; i++) {
        k_gemm_layer<<<TC_GRID, 128>>>(asrc + (size_t)i * DH,
                                       adst + (size_t)i * DH, 1 + i);
        k_agg<<<(NN + 7) / 8, 256>>>(bg, i);
    }

    // pooling + output head
    k_pool<<<(NN + 255) / 256, 128>>>(batch);
    k_final<<<GG, 64>>>(W2, b2, out);
}